// round 12
// baseline (speedup 1.0000x reference)
#include <cuda_runtime.h>
#include <math.h>

// Problem constants
#define TT 1000
#define BB 32
#define NN 2048
#define NC2 1024                 // uint2 (2-neuron) columns per batch
#define BN2 (BB * NC2)           // 32768 uint2 per timestep
#define NSEG 4
#define TSEG 250                 // timesteps per segment
#define UU 5                     // uint2 loads per prefetch group (250 = 50*5)
// Output layout (concatenated tuple, all f32):
#define OFF_FR 0
#define OFF_CV 65536
#define OFF_SY 131072
#define OFF_TS 131104
#define OFF_AN 196640

// Scratch (fully overwritten every launch; no init needed)
// Packed ISI per segment: x = first<<16 | last, y = total<<16 | sumg2
// (within a 250-step segment: first/last<=999, total<=250, sumg2<=62001<2^16)
__device__ float  g_pop_part[1024 * TSEG];  // [(b*4+seg)*8+chunk][tl]
__device__ uint2  g_isi[NSEG * BB * NN];    // packed per-segment ISI stats
__device__ uchar2 g_tot[NSEG * BB * NC2];   // [seg][b][col] per-neuron totals

// ---------------------------------------------------------------------------
// Kernel 1: stream input once. grid = 32b x 4seg x 8chunk = 1024 blocks x 128.
// Each thread owns one uint2 column (2 neurons) for TSEG timesteps.
// ---------------------------------------------------------------------------
__device__ __forceinline__ void proc_group(
    const uint2* x, int tl0, int tbase, int lane, int w,
    int* last, int* first, int* total, int* sumg2, int (*pop_s)[TSEG])
{
    #pragma unroll
    for (int j = 0; j < UU; j++) {
        const int tl = tl0 + j;
        const int t  = tbase + tl;
        uint2 u = x[j];
        int s0 = (int)(u.x >> 29);   // 1.0f -> 1, 0.0f -> 0
        int s1 = (int)(u.y >> 29);
        unsigned psum = __reduce_add_sync(0xffffffffu, (unsigned)(s0 + s1));
        if (lane == 0) pop_s[w][tl] = (int)psum;

        if (s0) {
            if (last[0] >= 0) { int g = t - last[0]; sumg2[0] += g * g; }
            else              { first[0] = t; }
            last[0] = t; total[0]++;
        }
        if (s1) {
            if (last[1] >= 0) { int g = t - last[1]; sumg2[1] += g * g; }
            else              { first[1] = t; }
            last[1] = t; total[1]++;
        }
    }
}

__global__ __launch_bounds__(128, 8)
void spike_main(const float* __restrict__ in) {
    const int bid   = blockIdx.x;          // 0..1023
    const int b     = bid >> 5;            // batch
    const int seg   = (bid >> 3) & 3;      // time segment
    const int chunk = bid & 7;             // 128 uint2 columns each
    const int tid   = threadIdx.x;         // 0..127
    const int w     = tid >> 5;
    const int lane  = tid & 31;
    const int tbase = seg * TSEG;
    const int col   = (chunk << 7) | tid;  // uint2 column 0..1023

    __shared__ int pop_s[4][TSEG];         // 4 KB

    const uint2* p = (const uint2*)in + (size_t)tbase * BN2 + (size_t)b * NC2 + col;

    int last[2]  = {-1, -1};
    int first[2] = {-1, -1};
    int total[2] = {0, 0};
    int sumg2[2] = {0, 0};

    uint2 A[UU], Bf[UU];

    // Prime: group 0 -> A.  50 groups total: 25 ping-pong pairs.
    #pragma unroll
    for (int i = 0; i < UU; i++) A[i] = __ldcs(p + (size_t)i * BN2);

    #pragma unroll 1
    for (int gp = 0; gp < 25; gp++) {
        const int tA = gp * 2 * UU;
        const int tB = tA + UU;
        #pragma unroll
        for (int i = 0; i < UU; i++) Bf[i] = __ldcs(p + (size_t)(tB + i) * BN2);
        proc_group(A, tA, tbase, lane, w, last, first, total, sumg2, pop_s);
        if (gp < 24) {
            const int tA2 = tB + UU;
            #pragma unroll
            for (int i = 0; i < UU; i++) A[i] = __ldcs(p + (size_t)(tA2 + i) * BN2);
        }
        proc_group(Bf, tB, tbase, lane, w, last, first, total, sumg2, pop_s);
    }

    // Packed per-neuron segment stats (2 consecutive uint2 per thread)
    const int nbase = (seg * BB + b) * NN + (col << 1);
    g_isi[nbase + 0] = make_uint2(
        (((unsigned)first[0] & 0xffffu) << 16) | ((unsigned)last[0] & 0xffffu),
        ((unsigned)total[0] << 16) | (unsigned)sumg2[0]);
    g_isi[nbase + 1] = make_uint2(
        (((unsigned)first[1] & 0xffffu) << 16) | ((unsigned)last[1] & 0xffffu),
        ((unsigned)total[1] << 16) | (unsigned)sumg2[1]);
    // Compact per-neuron totals for the active-count path
    g_tot[(seg * BB + b) * NC2 + col] = make_uchar2((unsigned char)total[0],
                                                    (unsigned char)total[1]);

    __syncthreads();
    // Reduce 4 warp rows -> per-block population partial
    #pragma unroll
    for (int r = 0; r < 2; r++) {
        int tl = tid + r * 128;
        if (tl < TSEG) {
            int s = pop_s[0][tl] + pop_s[1][tl] + pop_s[2][tl] + pop_s[3][tl];
            g_pop_part[bid * TSEG + tl] = (float)s;
        }
    }
}

// ---------------------------------------------------------------------------
// Kernel 2 (fused tail): blocks 0..31 = per-batch sync (longest path, first);
// blocks 32..543 = per-neuron merge (512 blocks x 128 threads).
// ---------------------------------------------------------------------------
__global__ __launch_bounds__(256)
void spike_tail(float* __restrict__ out) {
    const int gbid = blockIdx.x;
    const int tid  = threadIdx.x;
    const int w    = tid >> 5;
    const int lane = tid & 31;

    if (gbid < 32) {
        // ---------------- sync: one batch per block (256 threads) ----------
        const int b = gbid;

        __shared__ float pop[TT];
        __shared__ float red1[8], red2[8], redc[8];
        __shared__ int   act_s[8];

        // Active neurons from byte totals: 512 uints per (seg,b);
        // OR across segments, count nonzero bytes.
        {
            const unsigned* tp = (const unsigned*)g_tot;
            unsigned v0 = 0, v1 = 0;
            #pragma unroll
            for (int sg = 0; sg < NSEG; sg++) {
                const unsigned* base = tp + (sg * BB + b) * 512;
                v0 |= base[tid];
                v1 |= base[tid + 256];
            }
            int act = (__popc(__vcmpgtu4(v0, 0u)) + __popc(__vcmpgtu4(v1, 0u))) >> 3;
            act = (int)__reduce_add_sync(0xffffffffu, (unsigned)act);
            if (lane == 0) act_s[w] = act;
        }

        // Assemble pop[t] (all 32 loads independent)
        #pragma unroll
        for (int r = 0; r < 4; r++) {
            int t = tid + r * 256;
            if (t < TT) {
                int sg = t / TSEG;
                int tl = t - sg * TSEG;
                int rowb = (b * 4 + sg) * 8;
                float s = 0.0f;
                #pragma unroll
                for (int k = 0; k < 8; k++)
                    s += g_pop_part[(rowb + k) * TSEG + tl];
                pop[t] = s;
            }
        }
        __syncthreads();

        // Float autocorr with fixed offset c=1024 (pop ~ Binomial(2048, 0.5)):
        // num = Sc - S1^2/T, den = S2 - S1^2/T on centered values (exact shift-
        // invariance of circular covariance).
        const float c = 1024.0f;
        float s1 = 0.0f, s2 = 0.0f, sc = 0.0f;
        #pragma unroll
        for (int r = 0; r < 4; r++) {
            int t = tid + r * 256;
            if (t < TT) {
                float x  = pop[t] - c;
                int tp2 = (t == 0) ? (TT - 1) : (t - 1);
                float xp = pop[tp2] - c;
                s1 += x;
                s2 += x * x;
                sc += x * xp;
            }
        }
        #pragma unroll
        for (int o = 16; o > 0; o >>= 1) {
            s1 += __shfl_down_sync(0xffffffffu, s1, o);
            s2 += __shfl_down_sync(0xffffffffu, s2, o);
            sc += __shfl_down_sync(0xffffffffu, sc, o);
        }
        if (lane == 0) { red1[w] = s1; red2[w] = s2; redc[w] = sc; }
        __syncthreads();
        if (tid == 0) {
            double S1 = 0.0, S2 = 0.0, Sc = 0.0;
            int a = 0;
            #pragma unroll
            for (int k = 0; k < 8; k++) {
                S1 += (double)red1[k]; S2 += (double)red2[k];
                Sc += (double)redc[k]; a += act_s[k];
            }
            double mt  = S1 * S1 / (double)TT;
            double num = Sc - mt;
            double den = S2 - mt;
            out[OFF_SY + b] = (den > 0.0) ? (float)(num / fmax(den, 1e-12)) : 0.0f;
            out[OFF_AN + b] = (float)a;
        }
    } else if (tid < 128) {
        // ---------------- merge: 128 neurons per block ----------------
        const int ng = (gbid - 32) * 128 + tid;   // global neuron 0..65535
        const int b  = ng >> 11;
        const int n  = ng & (NN - 1);

        uint2 segs[NSEG];
        #pragma unroll
        for (int sg = 0; sg < NSEG; sg++)
            segs[sg] = g_isi[(sg * BB + b) * NN + n];

        int first = -1, last = -1, total = 0, sumg2 = 0;
        #pragma unroll
        for (int sg = 0; sg < NSEG; sg++) {
            int vt = (int)(segs[sg].y >> 16);          // segment total
            if (vt > 0) {
                int vf = (int)(segs[sg].x >> 16);       // segment first
                int vl = (int)(segs[sg].x & 0xffffu);   // segment last
                int vs = (int)(segs[sg].y & 0xffffu);   // segment sumg2
                if (total > 0) { int g = vf - last; sumg2 += g * g; }
                else           { first = vf; }
                last   = vl;
                total += vt;
                sumg2 += vs;
            }
        }

        const int idx = b * NN + n;
        float tot = (float)total;
        out[OFF_FR + idx] = tot / (TT * 0.001f);
        out[OFF_TS + idx] = tot;

        float cv = 0.0f;
        int cnt = total - 1;
        if (cnt >= 1) {
            float fc   = (float)cnt;
            float mean = (float)(last - first) / fc;
            float var  = ((float)sumg2 - fc * mean * mean) / fmaxf(fc - 1.0f, 1.0f);
            cv = sqrtf(fmaxf(var, 0.0f)) / fmaxf(mean, 1e-12f);
        }
        out[OFF_CV + idx] = cv;
    }
}

extern "C" void kernel_launch(void* const* d_in, const int* in_sizes, int n_in,
                              void* d_out, int out_size) {
    const float* in = (const float*)d_in[0];
    float* out = (float*)d_out;
    spike_main<<<1024, 128>>>(in);
    spike_tail<<<544, 256>>>(out);
}

// round 15
// speedup vs baseline: 1.0862x; 1.0862x over previous
#include <cuda_runtime.h>
#include <math.h>

// Problem constants
#define TT 1000
#define BB 32
#define NN 2048
#define NC2 1024                 // uint2 (2-neuron) columns per batch
#define BN2 (BB * NC2)           // 32768 uint2 per timestep
#define NSEG 4
#define TSEG 250                 // timesteps per segment
#define UU 5                     // uint2 loads per prefetch group (250 = 50*5)
// Output layout (concatenated tuple, all f32):
#define OFF_FR 0
#define OFF_CV 65536
#define OFF_SY 131072
#define OFF_TS 131104
#define OFF_AN 196640

// Scratch (fully overwritten every launch; no init needed)
// Packed ISI per segment: x = first<<16 | last, y = total<<16 | sumg2
__device__ float  g_pop_part[1024 * TSEG];  // [(b*4+seg)*8+chunk][tl]
__device__ uint2  g_isi[NSEG * BB * NN];    // packed per-segment ISI stats
__device__ uchar2 g_tot[NSEG * BB * NC2];   // [seg][b][col] per-neuron totals

// ---------------------------------------------------------------------------
// Kernel 1: stream input once. grid = 32b x 4seg x 8chunk = 1024 blocks x 128.
// Each thread owns one uint2 column (2 neurons) for TSEG timesteps.
// 3-deep buffer rotation: every load has ~2 proc-groups of slack (~1200 cyc).
// ---------------------------------------------------------------------------
__device__ __forceinline__ void proc_group(
    const uint2* x, int tl0, int tbase, int lane, int w,
    int* last, int* first, int* total, int* sumg2, int (*pop_s)[TSEG])
{
    #pragma unroll
    for (int j = 0; j < UU; j++) {
        const int tl = tl0 + j;
        const int t  = tbase + tl;
        uint2 u = x[j];
        int s0 = (int)(u.x >> 29);   // 1.0f -> 1, 0.0f -> 0
        int s1 = (int)(u.y >> 29);
        unsigned psum = __reduce_add_sync(0xffffffffu, (unsigned)(s0 + s1));
        if (lane == 0) pop_s[w][tl] = (int)psum;

        if (s0) {
            if (last[0] >= 0) { int g = t - last[0]; sumg2[0] += g * g; }
            else              { first[0] = t; }
            last[0] = t; total[0]++;
        }
        if (s1) {
            if (last[1] >= 0) { int g = t - last[1]; sumg2[1] += g * g; }
            else              { first[1] = t; }
            last[1] = t; total[1]++;
        }
    }
}

__global__ __launch_bounds__(128, 7)
void spike_main(const float* __restrict__ in) {
    const int bid   = blockIdx.x;          // 0..1023
    const int b     = bid >> 5;            // batch
    const int seg   = (bid >> 3) & 3;      // time segment
    const int chunk = bid & 7;             // 128 uint2 columns each
    const int tid   = threadIdx.x;         // 0..127
    const int w     = tid >> 5;
    const int lane  = tid & 31;
    const int tbase = seg * TSEG;
    const int col   = (chunk << 7) | tid;  // uint2 column 0..1023

    __shared__ int pop_s[4][TSEG];         // 4 KB

    const uint2* p = (const uint2*)in + (size_t)tbase * BN2 + (size_t)b * NC2 + col;

    int last[2]  = {-1, -1};
    int first[2] = {-1, -1};
    int total[2] = {0, 0};
    int sumg2[2] = {0, 0};

    uint2 A[UU], Bf[UU], C[UU];

    // Prime groups 0,1 -> A,B. 50 groups of 5 timesteps.
    #pragma unroll
    for (int i = 0; i < UU; i++) A[i]  = __ldcs(p + (size_t)i * BN2);
    #pragma unroll
    for (int i = 0; i < UU; i++) Bf[i] = __ldcs(p + (size_t)(UU + i) * BN2);

    // 16 iterations: procs g0..g47, loads g2..g49 (all indices valid).
    #pragma unroll 1
    for (int k = 0; k < 16; k++) {
        const int g0 = 3 * k * UU;               // group 3k (in A)
        // load group 3k+2 -> C
        #pragma unroll
        for (int i = 0; i < UU; i++) C[i] = __ldcs(p + (size_t)(g0 + 2 * UU + i) * BN2);
        proc_group(A, g0, tbase, lane, w, last, first, total, sumg2, pop_s);
        // load group 3k+3 -> A
        #pragma unroll
        for (int i = 0; i < UU; i++) A[i] = __ldcs(p + (size_t)(g0 + 3 * UU + i) * BN2);
        proc_group(Bf, g0 + UU, tbase, lane, w, last, first, total, sumg2, pop_s);
        // load group 3k+4 -> B
        #pragma unroll
        for (int i = 0; i < UU; i++) Bf[i] = __ldcs(p + (size_t)(g0 + 4 * UU + i) * BN2);
        proc_group(C, g0 + 2 * UU, tbase, lane, w, last, first, total, sumg2, pop_s);
    }
    // Tail: groups 48 (A), 49 (B) already loaded.
    proc_group(A,  48 * UU, tbase, lane, w, last, first, total, sumg2, pop_s);
    proc_group(Bf, 49 * UU, tbase, lane, w, last, first, total, sumg2, pop_s);

    // Packed per-neuron segment stats (2 consecutive uint2 per thread)
    const int nbase = (seg * BB + b) * NN + (col << 1);
    g_isi[nbase + 0] = make_uint2(
        (((unsigned)first[0] & 0xffffu) << 16) | ((unsigned)last[0] & 0xffffu),
        ((unsigned)total[0] << 16) | (unsigned)sumg2[0]);
    g_isi[nbase + 1] = make_uint2(
        (((unsigned)first[1] & 0xffffu) << 16) | ((unsigned)last[1] & 0xffffu),
        ((unsigned)total[1] << 16) | (unsigned)sumg2[1]);
    g_tot[(seg * BB + b) * NC2 + col] = make_uchar2((unsigned char)total[0],
                                                    (unsigned char)total[1]);

    __syncthreads();
    // Reduce 4 warp rows -> per-block population partial
    #pragma unroll
    for (int r = 0; r < 2; r++) {
        int tl = tid + r * 128;
        if (tl < TSEG) {
            int s = pop_s[0][tl] + pop_s[1][tl] + pop_s[2][tl] + pop_s[3][tl];
            g_pop_part[bid * TSEG + tl] = (float)s;
        }
    }
}

// ---------------------------------------------------------------------------
// Kernel 2 (fused tail): blocks 0..31 = per-batch sync (longest path, first);
// blocks 32..543 = per-neuron merge (512 blocks x 128 active threads).
// ---------------------------------------------------------------------------
__global__ __launch_bounds__(256)
void spike_tail(float* __restrict__ out) {
    const int gbid = blockIdx.x;
    const int tid  = threadIdx.x;
    const int w    = tid >> 5;
    const int lane = tid & 31;

    if (gbid < 32) {
        // ---------------- sync: one batch per block (256 threads) ----------
        const int b = gbid;

        __shared__ float pop[TT];
        __shared__ float red1[8], red2[8], redc[8];
        __shared__ int   act_s[8];

        // Active neurons from byte totals: 512 uints per (seg,b)
        {
            const unsigned* tp = (const unsigned*)g_tot;
            unsigned v0 = 0, v1 = 0;
            #pragma unroll
            for (int sg = 0; sg < NSEG; sg++) {
                const unsigned* base = tp + (sg * BB + b) * 512;
                v0 |= base[tid];
                v1 |= base[tid + 256];
            }
            int act = (__popc(__vcmpgtu4(v0, 0u)) + __popc(__vcmpgtu4(v1, 0u))) >> 3;
            act = (int)__reduce_add_sync(0xffffffffu, (unsigned)act);
            if (lane == 0) act_s[w] = act;
        }

        // Assemble pop[t]
        #pragma unroll
        for (int r = 0; r < 4; r++) {
            int t = tid + r * 256;
            if (t < TT) {
                int sg = t / TSEG;
                int tl = t - sg * TSEG;
                int rowb = (b * 4 + sg) * 8;
                float s = 0.0f;
                #pragma unroll
                for (int k = 0; k < 8; k++)
                    s += g_pop_part[(rowb + k) * TSEG + tl];
                pop[t] = s;
            }
        }
        __syncthreads();

        // Float autocorr with fixed offset c=1024 (shift-invariant covariance)
        const float c = 1024.0f;
        float s1 = 0.0f, s2 = 0.0f, sc = 0.0f;
        #pragma unroll
        for (int r = 0; r < 4; r++) {
            int t = tid + r * 256;
            if (t < TT) {
                float x  = pop[t] - c;
                int tp2 = (t == 0) ? (TT - 1) : (t - 1);
                float xp = pop[tp2] - c;
                s1 += x;
                s2 += x * x;
                sc += x * xp;
            }
        }
        #pragma unroll
        for (int o = 16; o > 0; o >>= 1) {
            s1 += __shfl_down_sync(0xffffffffu, s1, o);
            s2 += __shfl_down_sync(0xffffffffu, s2, o);
            sc += __shfl_down_sync(0xffffffffu, sc, o);
        }
        if (lane == 0) { red1[w] = s1; red2[w] = s2; redc[w] = sc; }
        __syncthreads();
        if (tid == 0) {
            double S1 = 0.0, S2 = 0.0, Sc = 0.0;
            int a = 0;
            #pragma unroll
            for (int k = 0; k < 8; k++) {
                S1 += (double)red1[k]; S2 += (double)red2[k];
                Sc += (double)redc[k]; a += act_s[k];
            }
            double mt  = S1 * S1 / (double)TT;
            double num = Sc - mt;
            double den = S2 - mt;
            out[OFF_SY + b] = (den > 0.0) ? (float)(num / fmax(den, 1e-12)) : 0.0f;
            out[OFF_AN + b] = (float)a;
        }
    } else if (tid < 128) {
        // ---------------- merge: 128 neurons per block ----------------
        const int ng = (gbid - 32) * 128 + tid;   // global neuron 0..65535
        const int b  = ng >> 11;
        const int n  = ng & (NN - 1);

        uint2 segs[NSEG];
        #pragma unroll
        for (int sg = 0; sg < NSEG; sg++)
            segs[sg] = g_isi[(sg * BB + b) * NN + n];

        int first = -1, last = -1, total = 0, sumg2 = 0;
        #pragma unroll
        for (int sg = 0; sg < NSEG; sg++) {
            int vt = (int)(segs[sg].y >> 16);          // segment total
            if (vt > 0) {
                int vf = (int)(segs[sg].x >> 16);       // segment first
                int vl = (int)(segs[sg].x & 0xffffu);   // segment last
                int vs = (int)(segs[sg].y & 0xffffu);   // segment sumg2
                if (total > 0) { int g = vf - last; sumg2 += g * g; }
                else           { first = vf; }
                last   = vl;
                total += vt;
                sumg2 += vs;
            }
        }

        const int idx = b * NN + n;
        float tot = (float)total;
        out[OFF_FR + idx] = tot / (TT * 0.001f);
        out[OFF_TS + idx] = tot;

        float cv = 0.0f;
        int cnt = total - 1;
        if (cnt >= 1) {
            float fc   = (float)cnt;
            float mean = (float)(last - first) / fc;
            float var  = ((float)sumg2 - fc * mean * mean) / fmaxf(fc - 1.0f, 1.0f);
            cv = sqrtf(fmaxf(var, 0.0f)) / fmaxf(mean, 1e-12f);
        }
        out[OFF_CV + idx] = cv;
    }
}

extern "C" void kernel_launch(void* const* d_in, const int* in_sizes, int n_in,
                              void* d_out, int out_size) {
    const float* in = (const float*)d_in[0];
    float* out = (float*)d_out;
    spike_main<<<1024, 128>>>(in);
    spike_tail<<<544, 256>>>(out);
}